// round 14
// baseline (speedup 1.0000x reference)
#include <cuda_runtime.h>

#define NQ 900
#define NB 32
#define NC 91
#define TBTH 0.9f

// ---- k1 block layout: giou blocks then copy blocks ----
#define GB_PER_BATCH 25
#define RPB 18                                  // 450/18 = 25 blocks per batch
#define GIOU_BLOCKS (NB * GB_PER_BATCH)         // 800
#define ECAP 256

#define COPY_BLOCKS 448
#define K1_BLOCKS (GIOU_BLOCKS + COPY_BLOCKS)   // 1248

#define LOG_V8 (NB * NQ * NC / 8)          // 327,600 v8 chunks
#define LOG_OFF_F (NB * NQ * 4)            // 115,200
#define ADJ_OFF_F (LOG_OFF_F + NB * NQ * NC)
#define ADJ_BYTES ((size_t)NB * NQ * NQ * 4)   // 103,680,000

#define MAXE 1024
#define MAXM 256

// device scratch (allocation-free; g_done zero at load, self-resets each call)
__device__ unsigned int g_bedge[GIOU_BLOCKS * ECAP];
__device__ int g_bcnt[GIOU_BLOCKS];
__device__ int g_done[NB];

__device__ __forceinline__ void stg_v8(float* p, const float* v) {
    asm volatile("st.global.v8.f32 [%0], {%1,%2,%3,%4,%5,%6,%7,%8};"
                 :: "l"(p), "f"(v[0]), "f"(v[1]), "f"(v[2]), "f"(v[3]),
                    "f"(v[4]), "f"(v[5]), "f"(v[6]), "f"(v[7]) : "memory");
}
__device__ __forceinline__ void ldg_v8(float* v, const float* p) {
    asm volatile("ld.global.v8.f32 {%0,%1,%2,%3,%4,%5,%6,%7}, [%8];"
                 : "=f"(v[0]), "=f"(v[1]), "=f"(v[2]), "=f"(v[3]),
                   "=f"(v[4]), "=f"(v[5]), "=f"(v[6]), "=f"(v[7]) : "l"(p));
}

// ======================= K1: giou + fused CC/agg/diag/patch | logits copy ===========
// Runs AFTER the adj memset node (graph edge), so diag/patch stores are safe.
__global__ void __launch_bounds__(256) k1(const float4* __restrict__ bboxes,
                                          const float* __restrict__ logits,
                                          float* __restrict__ out) {
    __shared__ __align__(16) unsigned char sbuf[22400];
    __shared__ int s_cnt, s_changed, s_nm, s_last;

    const int u = blockIdx.x;
    const int tid = threadIdx.x;

    if (u >= GIOU_BLOCKS) {
        // ---------- logits pass-through: 256-bit ld/st ----------
        const int cu = u - GIOU_BLOCKS;
        float* dst = out + LOG_OFF_F;
        const int stride = COPY_BLOCKS * 256;
        int idx = cu * 256 + tid;
        #pragma unroll
        for (int rep = 0; rep < 3; rep++) {
            if (idx < LOG_V8) {
                float v[8];
                ldg_v8(v, logits + (size_t)idx * 8);
                stg_v8(dst + (size_t)idx * 8, v);
            }
            idx += stride;
        }
        return;
    }

    // ---------------- GIoU edge detection ----------------
    {
        float* sx1 = (float*)(sbuf + 0);
        float* sy1 = (float*)(sbuf + 3600);
        float* sx2 = (float*)(sbuf + 7200);
        float* sy2 = (float*)(sbuf + 10800);
        float* sa  = (float*)(sbuf + 14400);

        const int b = u / GB_PER_BATCH;
        const int blk = u % GB_PER_BATCH;
        if (tid == 0) { s_cnt = 0; s_nm = 0; }

        for (int i = tid; i < NQ; i += 256) {
            float4 bb = bboxes[b * NQ + i];
            float hw = 0.5f * bb.z, hh = 0.5f * bb.w;
            float x1 = bb.x - hw, y1 = bb.y - hh;
            float x2 = bb.x + hw, y2 = bb.y + hh;
            sx1[i] = x1; sy1[i] = y1; sx2[i] = x2; sy2[i] = y2;
            sa[i]  = (x2 - x1) * (y2 - y1);
        }
        __syncthreads();

        const int rp0 = blk * RPB;
        for (int rp = rp0; rp < rp0 + RPB; rp++) {
            #pragma unroll
            for (int half = 0; half < 2; half++) {
                int i = half ? (898 - rp) : rp;
                if (half && i == rp) break;
                const float x1i = sx1[i], y1i = sy1[i];
                const float x2i = sx2[i], y2i = sy2[i];
                const float ai  = sa[i];
                for (int j = i + 1 + tid; j < NQ; j += 256) {
                    float aj = sa[j];
                    float mn = fminf(ai, aj), mx = fmaxf(ai, aj);
                    if (mn < 0.8999f * mx) continue;   // giou <= iou <= min/max area
                    float wi = fminf(x2i, sx2[j]) - fmaxf(x1i, sx1[j]);
                    if (wi <= 0.0f) continue;
                    float hi = fminf(y2i, sy2[j]) - fmaxf(y1i, sy1[j]);
                    if (hi <= 0.0f) continue;
                    float inter = wi * hi;
                    float uni   = ai + aj - inter;
                    float we = fmaxf(x2i, sx2[j]) - fminf(x1i, sx1[j]);
                    float he = fmaxf(y2i, sy2[j]) - fminf(y1i, sy1[j]);
                    float ae = we * he;
                    float gf = __fdividef(inter, uni) - __fdividef(ae - uni, ae);
                    bool edge;
                    if (fabsf(gf - TBTH) > 3e-4f) {
                        edge = gf > TBTH;
                    } else {
                        float iou = inter / uni;       // bit-exact reference sequence
                        float q   = (ae - uni) / ae;
                        edge = (iou - q) > TBTH;
                    }
                    if (edge) {
                        int p = atomicAdd(&s_cnt, 1);
                        if (p < ECAP)
                            g_bedge[u * ECAP + p] = ((unsigned)i << 10) | (unsigned)j;
                    }
                }
            }
        }
        __threadfence();
        __syncthreads();
        if (tid == 0) {
            g_bcnt[u] = min(s_cnt, ECAP);
            __threadfence();
            int t = atomicAdd(&g_done[b], 1);
            s_last = (t == GB_PER_BATCH - 1);
            if (s_last) g_done[b] = 0;     // reset ticket for next graph replay
        }
        __syncthreads();
        if (!s_last) return;

        // -------- last block of batch: gather edges, CC, aggregation, diag+patch --------
        __threadfence();   // acquire: all batch edge data visible
        int*   lab   = (int*)(sbuf + 0);                       // 3600
        float* csum  = (float*)(sbuf + 3600);                  // 14400
        unsigned int* sedge = (unsigned int*)(sbuf + 3600);    // overlaps csum (dead after CC)
        float* ccnt  = (float*)(sbuf + 18000);                 // 3600
        short* mlist = (short*)(sbuf + 21600);                 // 512
        int*   scnt  = (int*)(sbuf + 22112);                   // 25 counts
        int*   coff  = scnt + GB_PER_BATCH;                    // 26 offsets

        for (int i = tid; i < NQ; i += 256) lab[i] = i;
        if (tid < GB_PER_BATCH) scnt[tid] = g_bcnt[b * GB_PER_BATCH + tid];
        __syncthreads();
        if (tid == 0) {
            int s = 0;
            #pragma unroll
            for (int k = 0; k < GB_PER_BATCH; k++) { coff[k] = s; s += scnt[k]; }
            coff[GB_PER_BATCH] = s;
        }
        __syncthreads();
        const int ne = min(coff[GB_PER_BATCH], MAXE);

        for (int e = tid; e < ne; e += 256) {
            int k = 0;
            #pragma unroll
            for (int t2 = 0; t2 < GB_PER_BATCH; t2++)
                if (e >= coff[t2 + 1]) k = t2 + 1;
            sedge[e] = g_bedge[(b * GB_PER_BATCH + k) * ECAP + (e - coff[k])];
        }
        __syncthreads();

        for (int it = 0; it < NQ; it++) {
            if (tid == 0) s_changed = 0;
            __syncthreads();
            for (int e = tid; e < ne; e += 256) {
                unsigned int pk = sedge[e];
                int i = pk >> 10, j = pk & 1023;
                int li = lab[i], lj = lab[j];
                int m = min(li, lj);
                if (li > m) { atomicMin(&lab[i], m); s_changed = 1; }
                if (lj > m) { atomicMin(&lab[j], m); s_changed = 1; }
            }
            __syncthreads();
            for (int i = tid; i < NQ; i += 256) {
                int l = lab[i], ll = lab[l];
                if (ll < l) { lab[i] = ll; s_changed = 1; }
            }
            __syncthreads();
            int ch = s_changed;
            __syncthreads();
            if (!ch) break;
        }

        // sedge dead from here; csum/ccnt initialize
        for (int i = tid; i < NQ; i += 256) {
            ccnt[i] = 0.0f;
            csum[4 * i + 0] = 0.0f; csum[4 * i + 1] = 0.0f;
            csum[4 * i + 2] = 0.0f; csum[4 * i + 3] = 0.0f;
        }
        __syncthreads();
        for (int i = tid; i < NQ; i += 256) {
            int l = lab[i];
            float4 bb = bboxes[b * NQ + i];
            atomicAdd(&ccnt[l], 1.0f);
            atomicAdd(&csum[4 * l + 0], bb.x);
            atomicAdd(&csum[4 * l + 1], bb.y);
            atomicAdd(&csum[4 * l + 2], bb.z);
            atomicAdd(&csum[4 * l + 3], bb.w);
        }
        __syncthreads();

        float4* oagg = (float4*)out;
        float* adj = out + ADJ_OFF_F;
        for (int i = tid; i < NQ; i += 256) {
            int l = lab[i];
            float d = ccnt[l] + 1e-6f;
            float4 o;
            o.x = csum[4 * l + 0] / d;
            o.y = csum[4 * l + 1] / d;
            o.z = csum[4 * l + 2] / d;
            o.w = csum[4 * l + 3] / d;
            oagg[b * NQ + i] = o;
            adj[((size_t)(b * NQ + i)) * NQ + i] = 1.0f;   // diagonal (memset zeroed adj)
            if (ccnt[l] > 1.5f) {
                int p = atomicAdd(&s_nm, 1);
                if (p < MAXM) mlist[p] = (short)i;
            }
        }
        __syncthreads();
        const int nm = min(s_nm, MAXM);

        // off-diagonal 1.0s for multi-member components (direct store)
        for (int p = tid; p < nm * nm; p += 256) {
            int a = mlist[p / nm];
            int c = mlist[p % nm];
            if (a != c && lab[a] == lab[c])
                adj[((size_t)(b * NQ + a)) * NQ + c] = 1.0f;
        }
    }
}

extern "C" void kernel_launch(void* const* d_in, const int* in_sizes, int n_in,
                              void* d_out, int out_size) {
    const float4* bboxes = (const float4*)d_in[0];   // [32,900,4] fp32
    const float*  logits = (const float*)d_in[1];    // [32,900,91] fp32
    float* out = (float*)d_out;                      // agg | logits | adj

    // Node 1: driver-optimized zero-fill of the adjacency region (graph memset node)
    cudaMemsetAsync(out + ADJ_OFF_F, 0, ADJ_BYTES, 0);
    // Node 2: everything else (ordered after memset by the graph edge)
    k1<<<K1_BLOCKS, 256>>>(bboxes, logits, out);
}

// round 15
// speedup vs baseline: 1.5150x; 1.5150x over previous
#include <cuda_runtime.h>

#define NQ 900
#define NB 32
#define NC 91
#define TBTH 0.9f

// ---- K1 block-range layout: giou first (overlaps fill), fill, copy ----
#define GB_PER_BATCH 25
#define RPB 18                                  // 450/18 = 25 blocks per batch
#define GIOU_BLOCKS (NB * GB_PER_BATCH)         // 800
#define ECAP 256

#define ROWS_PER_FILL 8
#define FILL_BLOCKS (NB * NQ / ROWS_PER_FILL)   // 3600
#define COPY_BLOCKS 448
#define K1_BLOCKS (GIOU_BLOCKS + FILL_BLOCKS + COPY_BLOCKS)  // 4848

#define LOG_V8 (NB * NQ * NC / 8)          // 327,600 v8 chunks
#define LOG_OFF_F (NB * NQ * 4)            // 115,200
#define ADJ_OFF_F (LOG_OFF_F + NB * NQ * NC)

#define MAXE 1024
#define MAXM 256
#define PCAP 4096
#define QCAP 3072                          // candidate queue per giou block (exp ~860)

// device scratch (allocation-free; g_done zero at load, self-resets each call)
__device__ unsigned int g_bedge[GIOU_BLOCKS * ECAP];
__device__ int g_bcnt[GIOU_BLOCKS];
__device__ int g_done[NB];
__device__ unsigned int g_plist[NB * PCAP];
__device__ int g_np[NB];

__device__ __forceinline__ void stg_v8(float* p, const float* v) {
    asm volatile("st.global.v8.f32 [%0], {%1,%2,%3,%4,%5,%6,%7,%8};"
                 :: "l"(p), "f"(v[0]), "f"(v[1]), "f"(v[2]), "f"(v[3]),
                    "f"(v[4]), "f"(v[5]), "f"(v[6]), "f"(v[7]) : "memory");
}
__device__ __forceinline__ void ldg_v8(float* v, const float* p) {
    asm volatile("ld.global.v8.f32 {%0,%1,%2,%3,%4,%5,%6,%7}, [%8];"
                 : "=f"(v[0]), "=f"(v[1]), "=f"(v[2]), "=f"(v[3]),
                   "=f"(v[4]), "=f"(v[5]), "=f"(v[6]), "=f"(v[7]) : "l"(p));
}

// ======================= K1: giou(2-phase)+CC | adj fill+diag (v8) | logits copy (v8) ==========
__global__ void __launch_bounds__(256) k1(const float4* __restrict__ bboxes,
                                          const float* __restrict__ logits,
                                          float* __restrict__ out) {
    __shared__ __align__(16) unsigned char sbuf[30336];
    __shared__ int s_cnt, s_changed, s_nm, s_np, s_last, s_qn;

    const int u = blockIdx.x;
    const int tid = threadIdx.x;

    if (u >= GIOU_BLOCKS && u < GIOU_BLOCKS + FILL_BLOCKS) {
        // ---------- adj fill: 256-bit stores, 8 rows (900 v8 chunks) per block ----------
        const int row0 = (u - GIOU_BLOCKS) * ROWS_PER_FILL;
        float* base = out + ADJ_OFF_F + (size_t)row0 * NQ;
        int dflat[ROWS_PER_FILL];
        #pragma unroll
        for (int r = 0; r < ROWS_PER_FILL; r++)
            dflat[r] = r * NQ + ((row0 + r) % NQ);
        #pragma unroll
        for (int k = 0; k < 4; k++) {
            int c = tid + k * 256;               // v8 chunk index, 900 per block
            if (c < 900) {
                float v[8] = {0.f, 0.f, 0.f, 0.f, 0.f, 0.f, 0.f, 0.f};
                #pragma unroll
                for (int r = 0; r < ROWS_PER_FILL; r++)
                    if ((dflat[r] >> 3) == c) v[dflat[r] & 7] = 1.0f;
                stg_v8(base + (size_t)c * 8, v);
            }
        }
        return;
    }

    if (u >= GIOU_BLOCKS) {
        // ---------- logits pass-through: 256-bit ld/st ----------
        const int cu = u - GIOU_BLOCKS - FILL_BLOCKS;
        float* dst = out + LOG_OFF_F;
        const int stride = COPY_BLOCKS * 256;
        int idx = cu * 256 + tid;
        #pragma unroll
        for (int rep = 0; rep < 3; rep++) {
            if (idx < LOG_V8) {
                float v[8];
                ldg_v8(v, logits + (size_t)idx * 8);
                stg_v8(dst + (size_t)idx * 8, v);
            }
            idx += stride;
        }
        return;
    }

    // ---------------- GIoU edge detection (two-phase) ----------------
    {
        float* sx1 = (float*)(sbuf + 0);
        float* sy1 = (float*)(sbuf + 3600);
        float* sx2 = (float*)(sbuf + 7200);
        float* sy2 = (float*)(sbuf + 10800);
        float* sa  = (float*)(sbuf + 14400);
        unsigned int* q = (unsigned int*)(sbuf + 18000);   // QCAP entries

        const int b = u / GB_PER_BATCH;
        const int blk = u % GB_PER_BATCH;
        if (tid == 0) { s_cnt = 0; s_nm = 0; s_np = 0; s_qn = 0; }

        for (int i = tid; i < NQ; i += 256) {
            float4 bb = bboxes[b * NQ + i];
            float hw = 0.5f * bb.z, hh = 0.5f * bb.w;
            float x1 = bb.x - hw, y1 = bb.y - hh;
            float x2 = bb.x + hw, y2 = bb.y + hh;
            sx1[i] = x1; sy1[i] = y1; sx2[i] = x2; sy2[i] = y2;
            sa[i]  = (x2 - x1) * (y2 - y1);
        }
        __syncthreads();

        // ---- Phase 1: area-window screen (superset of original prune-pass set) ----
        const float4* sa4 = (const float4*)sa;   // 225 aligned chunks
        const int rp0 = blk * RPB;
        for (int rp = rp0; rp < rp0 + RPB; rp++) {
            #pragma unroll
            for (int half = 0; half < 2; half++) {
                int i = half ? (898 - rp) : rp;
                if (half && i == rp) break;
                const float ai = sa[i];
                const float lo = 0.8999f * ai;
                const float hi = ai * 1.11125f;   // > ai/0.8999, inclusive
                const int c0 = (i + 1) >> 2;
                for (int c = c0 + tid; c < 225; c += 256) {
                    float4 a4 = sa4[c];
                    int j = c << 2;
                    if (j     > i && a4.x >= lo && a4.x <= hi) {
                        int p = atomicAdd(&s_qn, 1);
                        if (p < QCAP) q[p] = ((unsigned)i << 10) | (unsigned)j;
                    }
                    if (j + 1 > i && a4.y >= lo && a4.y <= hi) {
                        int p = atomicAdd(&s_qn, 1);
                        if (p < QCAP) q[p] = ((unsigned)i << 10) | (unsigned)(j + 1);
                    }
                    if (j + 2 > i && a4.z >= lo && a4.z <= hi) {
                        int p = atomicAdd(&s_qn, 1);
                        if (p < QCAP) q[p] = ((unsigned)i << 10) | (unsigned)(j + 2);
                    }
                    if (j + 3 > i && a4.w >= lo && a4.w <= hi) {
                        int p = atomicAdd(&s_qn, 1);
                        if (p < QCAP) q[p] = ((unsigned)i << 10) | (unsigned)(j + 3);
                    }
                }
            }
        }
        __syncthreads();

        // ---- Phase 2: full GIoU on candidates ----
        const int qn = min(s_qn, QCAP);
        for (int t = tid; t < qn; t += 256) {
            unsigned pk = q[t];
            int i = pk >> 10, j = pk & 1023;
            float wi = fminf(sx2[i], sx2[j]) - fmaxf(sx1[i], sx1[j]);
            if (wi <= 0.0f) continue;
            float hgt = fminf(sy2[i], sy2[j]) - fmaxf(sy1[i], sy1[j]);
            if (hgt <= 0.0f) continue;
            float inter = wi * hgt;
            float uni   = sa[i] + sa[j] - inter;
            float we = fmaxf(sx2[i], sx2[j]) - fminf(sx1[i], sx1[j]);
            float he = fmaxf(sy2[i], sy2[j]) - fminf(sy1[i], sy1[j]);
            float ae = we * he;
            float gf = __fdividef(inter, uni) - __fdividef(ae - uni, ae);
            bool edge;
            if (fabsf(gf - TBTH) > 3e-4f) {
                edge = gf > TBTH;
            } else {
                float iou = inter / uni;       // bit-exact reference sequence
                float qq  = (ae - uni) / ae;
                edge = (iou - qq) > TBTH;
            }
            if (edge) {
                int p = atomicAdd(&s_cnt, 1);
                if (p < ECAP) g_bedge[u * ECAP + p] = pk;
            }
        }
        __threadfence();
        __syncthreads();
        if (tid == 0) {
            g_bcnt[u] = min(s_cnt, ECAP);
            __threadfence();
            int t = atomicAdd(&g_done[b], 1);
            s_last = (t == GB_PER_BATCH - 1);
            if (s_last) g_done[b] = 0;     // reset ticket for next graph replay
        }
        __syncthreads();
        if (!s_last) return;

        // -------- last block of batch: gather edges, CC, aggregation, patch list --------
        __threadfence();   // acquire: all batch edge data visible
        int*   lab   = (int*)(sbuf + 0);                       // 3600
        float* csum  = (float*)(sbuf + 3600);                  // 14400
        unsigned int* sedge = (unsigned int*)(sbuf + 3600);    // overlaps csum (dead after CC)
        float* ccnt  = (float*)(sbuf + 18000);                 // 3600
        short* mlist = (short*)(sbuf + 21600);                 // 512
        int*   scnt  = (int*)(sbuf + 22112);                   // 25 counts
        int*   coff  = scnt + GB_PER_BATCH;                    // 26 offsets

        for (int i = tid; i < NQ; i += 256) lab[i] = i;
        if (tid < GB_PER_BATCH) scnt[tid] = g_bcnt[b * GB_PER_BATCH + tid];
        __syncthreads();
        if (tid == 0) {
            int s = 0;
            #pragma unroll
            for (int k = 0; k < GB_PER_BATCH; k++) { coff[k] = s; s += scnt[k]; }
            coff[GB_PER_BATCH] = s;
        }
        __syncthreads();
        const int ne = min(coff[GB_PER_BATCH], MAXE);

        for (int e = tid; e < ne; e += 256) {
            int k = 0;
            #pragma unroll
            for (int t2 = 0; t2 < GB_PER_BATCH; t2++)
                if (e >= coff[t2 + 1]) k = t2 + 1;
            sedge[e] = g_bedge[(b * GB_PER_BATCH + k) * ECAP + (e - coff[k])];
        }
        __syncthreads();

        for (int it = 0; it < NQ; it++) {
            if (tid == 0) s_changed = 0;
            __syncthreads();
            for (int e = tid; e < ne; e += 256) {
                unsigned int pk = sedge[e];
                int i = pk >> 10, j = pk & 1023;
                int li = lab[i], lj = lab[j];
                int m = min(li, lj);
                if (li > m) { atomicMin(&lab[i], m); s_changed = 1; }
                if (lj > m) { atomicMin(&lab[j], m); s_changed = 1; }
            }
            __syncthreads();
            for (int i = tid; i < NQ; i += 256) {
                int l = lab[i], ll = lab[l];
                if (ll < l) { lab[i] = ll; s_changed = 1; }
            }
            __syncthreads();
            int ch = s_changed;
            __syncthreads();
            if (!ch) break;
        }

        // sedge dead from here; csum/ccnt initialize
        for (int i = tid; i < NQ; i += 256) {
            ccnt[i] = 0.0f;
            csum[4 * i + 0] = 0.0f; csum[4 * i + 1] = 0.0f;
            csum[4 * i + 2] = 0.0f; csum[4 * i + 3] = 0.0f;
        }
        __syncthreads();
        for (int i = tid; i < NQ; i += 256) {
            int l = lab[i];
            float4 bb = bboxes[b * NQ + i];
            atomicAdd(&ccnt[l], 1.0f);
            atomicAdd(&csum[4 * l + 0], bb.x);
            atomicAdd(&csum[4 * l + 1], bb.y);
            atomicAdd(&csum[4 * l + 2], bb.z);
            atomicAdd(&csum[4 * l + 3], bb.w);
        }
        __syncthreads();

        float4* oagg = (float4*)out;
        for (int i = tid; i < NQ; i += 256) {
            int l = lab[i];
            float d = ccnt[l] + 1e-6f;
            float4 o;
            o.x = csum[4 * l + 0] / d;
            o.y = csum[4 * l + 1] / d;
            o.z = csum[4 * l + 2] / d;
            o.w = csum[4 * l + 3] / d;
            oagg[b * NQ + i] = o;
            if (ccnt[l] > 1.5f) {
                int p = atomicAdd(&s_nm, 1);
                if (p < MAXM) mlist[p] = (short)i;
            }
        }
        __syncthreads();
        const int nm = min(s_nm, MAXM);

        // emit off-diagonal patch list (a,c) pairs, same-component, a != c
        for (int p = tid; p < nm * nm; p += 256) {
            int a = mlist[p / nm];
            int c = mlist[p % nm];
            if (a != c && lab[a] == lab[c]) {
                int pos = atomicAdd(&s_np, 1);
                if (pos < PCAP)
                    g_plist[b * PCAP + pos] = ((unsigned)a << 10) | (unsigned)c;
            }
        }
        __syncthreads();
        if (tid == 0) g_np[b] = min(s_np, PCAP);
    }
}

// ======================= K2: scatter off-diagonal 1.0s from patch list =======================
__global__ void __launch_bounds__(256) k2(float* __restrict__ out) {
    const int b = blockIdx.x;
    const int tid = threadIdx.x;
    float* adj = out + ADJ_OFF_F;

    const int np = g_np[b];
    for (int idx = tid; idx < np; idx += 256) {
        unsigned int pk = g_plist[b * PCAP + idx];
        int a = pk >> 10, c = pk & 1023;
        adj[((size_t)(b * NQ + a)) * NQ + c] = 1.0f;
    }
}

extern "C" void kernel_launch(void* const* d_in, const int* in_sizes, int n_in,
                              void* d_out, int out_size) {
    const float4* bboxes = (const float4*)d_in[0];   // [32,900,4] fp32
    const float*  logits = (const float*)d_in[1];    // [32,900,91] fp32
    float* out = (float*)d_out;                      // agg | logits | adj

    k1<<<K1_BLOCKS, 256>>>(bboxes, logits, out);
    k2<<<NB, 256>>>(out);
}

// round 16
// speedup vs baseline: 1.5262x; 1.0074x over previous
#include <cuda_runtime.h>

#define NQ 900
#define NB 32
#define NC 91
#define TBTH 0.9f

// ---- K1 block-range layout: giou first (overlaps fill), fill, copy ----
#define GB_PER_BATCH 25
#define RPB 18                                  // 450/18 = 25 blocks per batch
#define GIOU_BLOCKS (NB * GB_PER_BATCH)         // 800
#define ECAP 256

#define ROWS_PER_FILL 8
#define FILL_BLOCKS (NB * NQ / ROWS_PER_FILL)   // 3600
#define COPY_BLOCKS 448
#define K1_BLOCKS (GIOU_BLOCKS + FILL_BLOCKS + COPY_BLOCKS)  // 4848

#define LOG_V8 (NB * NQ * NC / 8)          // 327,600 v8 chunks
#define LOG_OFF_F (NB * NQ * 4)            // 115,200
#define ADJ_OFF_F (LOG_OFF_F + NB * NQ * NC)

#define MAXE 1024
#define MAXM 256
#define PCAP 4096
#define QCAP 3072                          // candidate queue per giou block (exp ~860)

// device scratch (allocation-free; g_done zero at load, self-resets each call)
__device__ unsigned int g_bedge[GIOU_BLOCKS * ECAP];
__device__ int g_bcnt[GIOU_BLOCKS];
__device__ int g_done[NB];
__device__ unsigned int g_plist[NB * PCAP];
__device__ int g_np[NB];

__device__ __forceinline__ void stg_v8(float* p, const float* v) {
    asm volatile("st.global.v8.f32 [%0], {%1,%2,%3,%4,%5,%6,%7,%8};"
                 :: "l"(p), "f"(v[0]), "f"(v[1]), "f"(v[2]), "f"(v[3]),
                    "f"(v[4]), "f"(v[5]), "f"(v[6]), "f"(v[7]) : "memory");
}
__device__ __forceinline__ void ldg_v8(float* v, const float* p) {
    asm volatile("ld.global.v8.f32 {%0,%1,%2,%3,%4,%5,%6,%7}, [%8];"
                 : "=f"(v[0]), "=f"(v[1]), "=f"(v[2]), "=f"(v[3]),
                   "=f"(v[4]), "=f"(v[5]), "=f"(v[6]), "=f"(v[7]) : "l"(p));
}

// ======================= K1: giou(2-phase)+CC | adj fill+diag (v8) | logits copy (v8) ==========
__global__ void __launch_bounds__(256) k1(const float4* __restrict__ bboxes,
                                          const float* __restrict__ logits,
                                          float* __restrict__ out) {
    __shared__ __align__(16) unsigned char sbuf[30336];
    __shared__ int s_cnt, s_changed, s_nm, s_np, s_last, s_qn;

    const int u = blockIdx.x;
    const int tid = threadIdx.x;

    if (u >= GIOU_BLOCKS && u < GIOU_BLOCKS + FILL_BLOCKS) {
        // ---------- adj fill: 256-bit stores, 8 rows (900 v8 chunks) per block ----------
        const int row0 = (u - GIOU_BLOCKS) * ROWS_PER_FILL;
        float* base = out + ADJ_OFF_F + (size_t)row0 * NQ;
        int dflat[ROWS_PER_FILL];
        #pragma unroll
        for (int r = 0; r < ROWS_PER_FILL; r++)
            dflat[r] = r * NQ + ((row0 + r) % NQ);
        #pragma unroll
        for (int k = 0; k < 4; k++) {
            int c = tid + k * 256;               // v8 chunk index, 900 per block
            if (c < 900) {
                float v[8] = {0.f, 0.f, 0.f, 0.f, 0.f, 0.f, 0.f, 0.f};
                #pragma unroll
                for (int r = 0; r < ROWS_PER_FILL; r++)
                    if ((dflat[r] >> 3) == c) v[dflat[r] & 7] = 1.0f;
                stg_v8(base + (size_t)c * 8, v);
            }
        }
        cudaTriggerProgrammaticLaunchCompletion();
        return;
    }

    if (u >= GIOU_BLOCKS) {
        // ---------- logits pass-through: 256-bit ld/st ----------
        const int cu = u - GIOU_BLOCKS - FILL_BLOCKS;
        float* dst = out + LOG_OFF_F;
        const int stride = COPY_BLOCKS * 256;
        int idx = cu * 256 + tid;
        #pragma unroll
        for (int rep = 0; rep < 3; rep++) {
            if (idx < LOG_V8) {
                float v[8];
                ldg_v8(v, logits + (size_t)idx * 8);
                stg_v8(dst + (size_t)idx * 8, v);
            }
            idx += stride;
        }
        cudaTriggerProgrammaticLaunchCompletion();
        return;
    }

    // ---------------- GIoU edge detection (two-phase) ----------------
    {
        float* sx1 = (float*)(sbuf + 0);
        float* sy1 = (float*)(sbuf + 3600);
        float* sx2 = (float*)(sbuf + 7200);
        float* sy2 = (float*)(sbuf + 10800);
        float* sa  = (float*)(sbuf + 14400);
        unsigned int* q = (unsigned int*)(sbuf + 18000);   // QCAP entries

        const int b = u / GB_PER_BATCH;
        const int blk = u % GB_PER_BATCH;
        if (tid == 0) { s_cnt = 0; s_nm = 0; s_np = 0; s_qn = 0; }

        for (int i = tid; i < NQ; i += 256) {
            float4 bb = bboxes[b * NQ + i];
            float hw = 0.5f * bb.z, hh = 0.5f * bb.w;
            float x1 = bb.x - hw, y1 = bb.y - hh;
            float x2 = bb.x + hw, y2 = bb.y + hh;
            sx1[i] = x1; sy1[i] = y1; sx2[i] = x2; sy2[i] = y2;
            sa[i]  = (x2 - x1) * (y2 - y1);
        }
        __syncthreads();

        // ---- Phase 1: area-window screen (superset of original prune-pass set) ----
        const float4* sa4 = (const float4*)sa;   // 225 aligned chunks
        const int rp0 = blk * RPB;
        for (int rp = rp0; rp < rp0 + RPB; rp++) {
            #pragma unroll
            for (int half = 0; half < 2; half++) {
                int i = half ? (898 - rp) : rp;
                if (half && i == rp) break;
                const float ai = sa[i];
                const float lo = 0.8999f * ai;
                const float hi = ai * 1.11125f;   // > ai/0.8999, inclusive
                const int c0 = (i + 1) >> 2;
                for (int c = c0 + tid; c < 225; c += 256) {
                    float4 a4 = sa4[c];
                    int j = c << 2;
                    if (j     > i && a4.x >= lo && a4.x <= hi) {
                        int p = atomicAdd(&s_qn, 1);
                        if (p < QCAP) q[p] = ((unsigned)i << 10) | (unsigned)j;
                    }
                    if (j + 1 > i && a4.y >= lo && a4.y <= hi) {
                        int p = atomicAdd(&s_qn, 1);
                        if (p < QCAP) q[p] = ((unsigned)i << 10) | (unsigned)(j + 1);
                    }
                    if (j + 2 > i && a4.z >= lo && a4.z <= hi) {
                        int p = atomicAdd(&s_qn, 1);
                        if (p < QCAP) q[p] = ((unsigned)i << 10) | (unsigned)(j + 2);
                    }
                    if (j + 3 > i && a4.w >= lo && a4.w <= hi) {
                        int p = atomicAdd(&s_qn, 1);
                        if (p < QCAP) q[p] = ((unsigned)i << 10) | (unsigned)(j + 3);
                    }
                }
            }
        }
        __syncthreads();

        // ---- Phase 2: full GIoU on candidates ----
        const int qn = min(s_qn, QCAP);
        for (int t = tid; t < qn; t += 256) {
            unsigned pk = q[t];
            int i = pk >> 10, j = pk & 1023;
            float wi = fminf(sx2[i], sx2[j]) - fmaxf(sx1[i], sx1[j]);
            if (wi <= 0.0f) continue;
            float hgt = fminf(sy2[i], sy2[j]) - fmaxf(sy1[i], sy1[j]);
            if (hgt <= 0.0f) continue;
            float inter = wi * hgt;
            float uni   = sa[i] + sa[j] - inter;
            float we = fmaxf(sx2[i], sx2[j]) - fminf(sx1[i], sx1[j]);
            float he = fmaxf(sy2[i], sy2[j]) - fminf(sy1[i], sy1[j]);
            float ae = we * he;
            float gf = __fdividef(inter, uni) - __fdividef(ae - uni, ae);
            bool edge;
            if (fabsf(gf - TBTH) > 3e-4f) {
                edge = gf > TBTH;
            } else {
                float iou = inter / uni;       // bit-exact reference sequence
                float qq  = (ae - uni) / ae;
                edge = (iou - qq) > TBTH;
            }
            if (edge) {
                int p = atomicAdd(&s_cnt, 1);
                if (p < ECAP) g_bedge[u * ECAP + p] = pk;
            }
        }
        __threadfence();
        __syncthreads();
        if (tid == 0) {
            g_bcnt[u] = min(s_cnt, ECAP);
            __threadfence();
            int t = atomicAdd(&g_done[b], 1);
            s_last = (t == GB_PER_BATCH - 1);
            if (s_last) g_done[b] = 0;     // reset ticket for next graph replay
        }
        __syncthreads();
        if (!s_last) {
            cudaTriggerProgrammaticLaunchCompletion();
            return;
        }

        // -------- last block of batch: gather edges, CC, aggregation, patch list --------
        __threadfence();   // acquire: all batch edge data visible
        int*   lab   = (int*)(sbuf + 0);                       // 3600
        float* csum  = (float*)(sbuf + 3600);                  // 14400
        unsigned int* sedge = (unsigned int*)(sbuf + 3600);    // overlaps csum (dead after CC)
        float* ccnt  = (float*)(sbuf + 18000);                 // 3600
        short* mlist = (short*)(sbuf + 21600);                 // 512
        int*   scnt  = (int*)(sbuf + 22112);                   // 25 counts
        int*   coff  = scnt + GB_PER_BATCH;                    // 26 offsets

        for (int i = tid; i < NQ; i += 256) lab[i] = i;
        if (tid < GB_PER_BATCH) scnt[tid] = g_bcnt[b * GB_PER_BATCH + tid];
        __syncthreads();
        if (tid == 0) {
            int s = 0;
            #pragma unroll
            for (int k = 0; k < GB_PER_BATCH; k++) { coff[k] = s; s += scnt[k]; }
            coff[GB_PER_BATCH] = s;
        }
        __syncthreads();
        const int ne = min(coff[GB_PER_BATCH], MAXE);

        for (int e = tid; e < ne; e += 256) {
            int k = 0;
            #pragma unroll
            for (int t2 = 0; t2 < GB_PER_BATCH; t2++)
                if (e >= coff[t2 + 1]) k = t2 + 1;
            sedge[e] = g_bedge[(b * GB_PER_BATCH + k) * ECAP + (e - coff[k])];
        }
        __syncthreads();

        for (int it = 0; it < NQ; it++) {
            if (tid == 0) s_changed = 0;
            __syncthreads();
            for (int e = tid; e < ne; e += 256) {
                unsigned int pk = sedge[e];
                int i = pk >> 10, j = pk & 1023;
                int li = lab[i], lj = lab[j];
                int m = min(li, lj);
                if (li > m) { atomicMin(&lab[i], m); s_changed = 1; }
                if (lj > m) { atomicMin(&lab[j], m); s_changed = 1; }
            }
            __syncthreads();
            for (int i = tid; i < NQ; i += 256) {
                int l = lab[i], ll = lab[l];
                if (ll < l) { lab[i] = ll; s_changed = 1; }
            }
            __syncthreads();
            int ch = s_changed;
            __syncthreads();
            if (!ch) break;
        }

        // sedge dead from here; csum/ccnt initialize
        for (int i = tid; i < NQ; i += 256) {
            ccnt[i] = 0.0f;
            csum[4 * i + 0] = 0.0f; csum[4 * i + 1] = 0.0f;
            csum[4 * i + 2] = 0.0f; csum[4 * i + 3] = 0.0f;
        }
        __syncthreads();
        for (int i = tid; i < NQ; i += 256) {
            int l = lab[i];
            float4 bb = bboxes[b * NQ + i];
            atomicAdd(&ccnt[l], 1.0f);
            atomicAdd(&csum[4 * l + 0], bb.x);
            atomicAdd(&csum[4 * l + 1], bb.y);
            atomicAdd(&csum[4 * l + 2], bb.z);
            atomicAdd(&csum[4 * l + 3], bb.w);
        }
        __syncthreads();

        float4* oagg = (float4*)out;
        for (int i = tid; i < NQ; i += 256) {
            int l = lab[i];
            float d = ccnt[l] + 1e-6f;
            float4 o;
            o.x = csum[4 * l + 0] / d;
            o.y = csum[4 * l + 1] / d;
            o.z = csum[4 * l + 2] / d;
            o.w = csum[4 * l + 3] / d;
            oagg[b * NQ + i] = o;
            if (ccnt[l] > 1.5f) {
                int p = atomicAdd(&s_nm, 1);
                if (p < MAXM) mlist[p] = (short)i;
            }
        }
        __syncthreads();
        const int nm = min(s_nm, MAXM);

        // emit off-diagonal patch list (a,c) pairs, same-component, a != c
        for (int p = tid; p < nm * nm; p += 256) {
            int a = mlist[p / nm];
            int c = mlist[p % nm];
            if (a != c && lab[a] == lab[c]) {
                int pos = atomicAdd(&s_np, 1);
                if (pos < PCAP)
                    g_plist[b * PCAP + pos] = ((unsigned)a << 10) | (unsigned)c;
            }
        }
        __syncthreads();
        if (tid == 0) g_np[b] = min(s_np, PCAP);
        __syncthreads();
        cudaTriggerProgrammaticLaunchCompletion();   // after g_np/g_plist writes
    }
}

// ======================= K2 (PDL): scatter off-diagonal 1.0s =======================
__global__ void __launch_bounds__(256) k2(float* __restrict__ out) {
    // Waits until all k1 CTAs have triggered (writes before trigger visible).
    cudaGridDependencySynchronize();

    const int b = blockIdx.x;
    const int tid = threadIdx.x;
    float* adj = out + ADJ_OFF_F;

    const int np = g_np[b];
    for (int idx = tid; idx < np; idx += 256) {
        unsigned int pk = g_plist[b * PCAP + idx];
        int a = pk >> 10, c = pk & 1023;
        adj[((size_t)(b * NQ + a)) * NQ + c] = 1.0f;
    }
}

extern "C" void kernel_launch(void* const* d_in, const int* in_sizes, int n_in,
                              void* d_out, int out_size) {
    const float4* bboxes = (const float4*)d_in[0];   // [32,900,4] fp32
    const float*  logits = (const float*)d_in[1];    // [32,900,91] fp32
    float* out = (float*)d_out;                      // agg | logits | adj

    k1<<<K1_BLOCKS, 256>>>(bboxes, logits, out);

    // k2 with Programmatic Dependent Launch: overlap launch latency with k1 tail.
    cudaLaunchConfig_t cfg = {};
    cfg.gridDim = dim3(NB, 1, 1);
    cfg.blockDim = dim3(256, 1, 1);
    cfg.dynamicSmemBytes = 0;
    cfg.stream = 0;
    cudaLaunchAttribute attr[1];
    attr[0].id = cudaLaunchAttributeProgrammaticStreamSerialization;
    attr[0].val.programmaticStreamSerializationAllowed = 1;
    cfg.attrs = attr;
    cfg.numAttrs = 1;
    cudaLaunchKernelEx(&cfg, k2, out);
}